// round 5
// baseline (speedup 1.0000x reference)
#include <cuda_runtime.h>
#include <cuda_bf16.h>

#define D_MODEL 1024
#define N_LEVELS 8
#define TPB 128                 // 4 warps, one row per block-iteration
#define NWARP 4
#define HALF_L 3.9960f          // 8 * (1 - 1e-3) / 2
#define LN_EPS 1e-5f
#define INV_D (1.0f / 1024.0f)

typedef unsigned long long ull;

// ---- packed f32x2 helpers (sm_103a FFMA2 path) ----
__device__ __forceinline__ ull pack2(float lo, float hi) {
    ull r; asm("mov.b64 %0, {%1, %2};" : "=l"(r) : "f"(lo), "f"(hi)); return r;
}
__device__ __forceinline__ void unpack2(ull p, float& lo, float& hi) {
    asm("mov.b64 {%0, %1}, %2;" : "=f"(lo), "=f"(hi) : "l"(p));
}
__device__ __forceinline__ ull fma2(ull a, ull b, ull c) {
    ull d; asm("fma.rn.f32x2 %0, %1, %2, %3;" : "=l"(d) : "l"(a), "l"(b), "l"(c)); return d;
}
__device__ __forceinline__ ull mul2(ull a, ull b) {
    ull d; asm("mul.rn.f32x2 %0, %1, %2;" : "=l"(d) : "l"(a), "l"(b)); return d;
}
__device__ __forceinline__ ull add2(ull a, ull b) {
    ull d; asm("add.rn.f32x2 %0, %1, %2;" : "=l"(d) : "l"(a), "l"(b)); return d;
}

__global__ __launch_bounds__(TPB, 4) void fsq_kernel(
    const float* __restrict__ x,     // [rows, 1024]
    const float* __restrict__ ln_w,  // [1024]
    const float* __restrict__ ln_b,  // [1024]
    const float* __restrict__ W,     // [8, 1024]
    float* __restrict__ out,         // [rows, 8]
    int rows)
{
    __shared__ float red[2][NWARP][12];  // double-buffered: 12 floats/warp, 48B stride (16B aligned)
    __shared__ float sG[N_LEVELS];
    __shared__ float sC[N_LEVELS];
    __shared__ float tmp[NWARP][16];

    const int t    = threadIdx.x;        // 0..127
    const int warp = t >> 5;
    const int lane = t & 31;

    // Thread's 8 columns: {4t..4t+3} and {512+4t..512+4t+3}  (two dense LDG.128 per row)
    const int base0 = 4 * t;
    const int base1 = 512 + 4 * t;

    // ---- Preamble: fold weights, pack into registers (once per block) ----
    ull pg[N_LEVELS][4];                 // g = ln_w ⊙ W[n,:], packed pairs
    float pG[N_LEVELS], pC[N_LEVELS];
    {
        float lw0[4], lb0[4], lw1[4], lb1[4];
        #pragma unroll
        for (int j = 0; j < 4; j++) {
            lw0[j] = ln_w[base0 + j]; lb0[j] = ln_b[base0 + j];
            lw1[j] = ln_w[base1 + j]; lb1[j] = ln_b[base1 + j];
        }
        #pragma unroll
        for (int n = 0; n < N_LEVELS; n++) {
            float g0[4], g1[4], sg = 0.f, sc = 0.f;
            #pragma unroll
            for (int j = 0; j < 4; j++) {
                float w0 = W[n * D_MODEL + base0 + j];
                float w1 = W[n * D_MODEL + base1 + j];
                g0[j] = lw0[j] * w0;  g1[j] = lw1[j] * w1;
                sg += g0[j] + g1[j];
                sc = fmaf(lb0[j], w0, sc);
                sc = fmaf(lb1[j], w1, sc);
            }
            pg[n][0] = pack2(g0[0], g0[1]);
            pg[n][1] = pack2(g0[2], g0[3]);
            pg[n][2] = pack2(g1[0], g1[1]);
            pg[n][3] = pack2(g1[2], g1[3]);
            pG[n] = sg;  pC[n] = sc;
        }
    }

    // ---- One-time block reduce of pG/pC (16 values) ----
    {
        float v[16];
        #pragma unroll
        for (int n = 0; n < N_LEVELS; n++) { v[n] = pG[n]; v[8 + n] = pC[n]; }
        #pragma unroll
        for (int off = 16; off > 0; off >>= 1)
            #pragma unroll
            for (int k = 0; k < 16; k++)
                v[k] += __shfl_xor_sync(0xFFFFFFFFu, v[k], off);
        if (lane == 0)
            #pragma unroll
            for (int k = 0; k < 16; k++) tmp[warp][k] = v[k];
        __syncthreads();
        if (t < 16) {
            float s = 0.f;
            #pragma unroll
            for (int w = 0; w < NWARP; w++) s += tmp[w][t];
            if (t < 8) sG[t] = s; else sC[t - 8] = s;
        }
        __syncthreads();
    }

    // ---- Main persistent loop over rows ----
    int par = 0;
    for (int row = blockIdx.x; row < rows; row += gridDim.x) {
        // Two dense 512B loads per warp; bits land pre-packed as f32 pairs.
        const double2* rp = reinterpret_cast<const double2*>(x + (size_t)row * D_MODEL);
        const double2 d0 = rp[t];
        const double2 d1 = rp[t + 128];
        const ull p0 = __double_as_longlong(d0.x);
        const ull p1 = __double_as_longlong(d0.y);
        const ull p2 = __double_as_longlong(d1.x);
        const ull p3 = __double_as_longlong(d1.y);

        // packed accumulation: sum, sumsq, 8 dots
        ull psum = add2(add2(p0, p1), add2(p2, p3));
        ull psq  = fma2(p1, p1, mul2(p0, p0));
        psq = fma2(p2, p2, psq);
        psq = fma2(p3, p3, psq);

        ull pd[N_LEVELS];
        #pragma unroll
        for (int n = 0; n < N_LEVELS; n++) {
            ull d = fma2(p1, pg[n][1], mul2(p0, pg[n][0]));
            d = fma2(p2, pg[n][2], d);
            d = fma2(p3, pg[n][3], d);
            pd[n] = d;
        }

        // unpack + horizontal add -> 10 scalars
        float v[10];
        {
            float lo, hi;
            unpack2(psum, lo, hi); v[0] = lo + hi;
            unpack2(psq,  lo, hi); v[1] = lo + hi;
            #pragma unroll
            for (int n = 0; n < N_LEVELS; n++) {
                unpack2(pd[n], lo, hi); v[2 + n] = lo + hi;
            }
        }

        // warp butterfly reduce (10 values x 5 steps)
        #pragma unroll
        for (int off = 16; off > 0; off >>= 1)
            #pragma unroll
            for (int k = 0; k < 10; k++)
                v[k] += __shfl_xor_sync(0xFFFFFFFFu, v[k], off);

        // vectorized per-warp writeback: 3 STS instead of 10
        if (lane == 0) {
            float* dst = red[par][warp];
            *reinterpret_cast<float4*>(dst)     = make_float4(v[0], v[1], v[2], v[3]);
            *reinterpret_cast<float4*>(dst + 4) = make_float4(v[4], v[5], v[6], v[7]);
            *reinterpret_cast<float2*>(dst + 8) = make_float2(v[8], v[9]);
        }
        __syncthreads();

        if (t < N_LEVELS) {
            float sum = 0.f, sumsq = 0.f, dt = 0.f;
            #pragma unroll
            for (int w = 0; w < NWARP; w++) {
                sum   += red[par][w][0];
                sumsq += red[par][w][1];
                dt    += red[par][w][2 + t];
            }
            float mean = sum * INV_D;
            float var  = fmaf(sumsq, INV_D, -mean * mean);
            float rstd = rsqrtf(var + LN_EPS);
            float z    = fmaf(rstd, fmaf(-mean, sG[t], dt), sC[t]);
            out[(size_t)row * N_LEVELS + t] = rintf(HALF_L * tanhf(z));
        }
        par ^= 1;
        // double buffer: the writer of this buffer two iterations from now
        // sits behind the next iteration's __syncthreads -> no hazard.
    }
}

extern "C" void kernel_launch(void* const* d_in, const int* in_sizes, int n_in,
                              void* d_out, int out_size) {
    const float* regrs = (const float*)d_in[0];
    const float* ln_w  = (const float*)d_in[1];
    const float* ln_b  = (const float*)d_in[2];
    const float* W     = (const float*)d_in[3];
    float* out = (float*)d_out;

    int rows = in_sizes[0] / D_MODEL;  // 32768
    int grid = 148 * 4;                // 4 persistent 128-thr blocks per SM
    if (grid > rows) grid = rows;

    fsq_kernel<<<grid, TPB>>>(regrs, ln_w, ln_b, W, out, rows);
}

// round 6
// speedup vs baseline: 2.1578x; 2.1578x over previous
#include <cuda_runtime.h>
#include <cstdint>

#define D_MODEL 1024
#define N_LEVELS 8
#define TPB 256
#define TILE_ROWS 256
#define CHUNK_COLS 64
#define N_CHUNKS 16                 // 1024 / 64
#define ROW_STRIDE_F 68             // 64 + 4 pad -> bank offset 4 per row
#define ROW_STRIDE_B (ROW_STRIDE_F * 4)          // 272 bytes
#define TILE_BUF_B (TILE_ROWS * ROW_STRIDE_B)    // 69632 bytes per buffer
#define HALF_L 3.9960f
#define LN_EPS 1e-5f
#define INV_D (1.0f / 1024.0f)

// smem layout (dynamic):
#define OFF_TILE 0                           // 2 buffers: 2*69632 = 139264
#define OFF_GW   (2 * TILE_BUF_B)            // 139264: longlong2 gw[256][8] = 32768
#define OFF_CV   (OFF_GW + 256 * 8 * 16)     // 172032: float G[8], C[8] = 64
#define OFF_TMP  (OFF_CV + 64)               // 172096: float tmp[8][16] = 512
#define SMEM_TOTAL (OFF_TMP + 512)           // 172608

typedef unsigned long long ull;

__device__ __forceinline__ ull pack2(float lo, float hi) {
    ull r; asm("mov.b64 %0, {%1, %2};" : "=l"(r) : "f"(lo), "f"(hi)); return r;
}
__device__ __forceinline__ void unpack2(ull p, float& lo, float& hi) {
    asm("mov.b64 {%0, %1}, %2;" : "=f"(lo), "=f"(hi) : "l"(p));
}
__device__ __forceinline__ ull fma2(ull a, ull b, ull c) {
    ull d; asm("fma.rn.f32x2 %0, %1, %2, %3;" : "=l"(d) : "l"(a), "l"(b), "l"(c)); return d;
}
__device__ __forceinline__ ull add2(ull a, ull b) {
    ull d; asm("add.rn.f32x2 %0, %1, %2;" : "=l"(d) : "l"(a), "l"(b)); return d;
}
__device__ __forceinline__ void cp16(uint32_t dst, const float* src) {
    asm volatile("cp.async.cg.shared.global [%0], [%1], 16;" :: "r"(dst), "l"(src));
}

__global__ __launch_bounds__(TPB, 1) void fsq_kernel(
    const float* __restrict__ x,     // [rows, 1024]
    const float* __restrict__ ln_w,  // [1024]
    const float* __restrict__ ln_b,  // [1024]
    const float* __restrict__ W,     // [8, 1024]
    float* __restrict__ out,         // [rows, 8]
    int rows)
{
    extern __shared__ char smem[];
    longlong2* gw  = (longlong2*)(smem + OFF_GW);     // [quad 0..255][level 0..7]
    float* sG      = (float*)(smem + OFF_CV);         // [8]
    float* sC      = (float*)(smem + OFF_CV) + 8;     // [8]
    float (*tmp)[16] = (float(*)[16])(smem + OFF_TMP);

    const int t = threadIdx.x;
    const int w = t >> 5, L = t & 31;

    // ================= preamble: G_n, C_n, centered weights g' =================
    float lw[4], lb[4], Wr[N_LEVELS][4];
    #pragma unroll
    for (int j = 0; j < 4; j++) { lw[j] = ln_w[4*t + j]; lb[j] = ln_b[4*t + j]; }
    {
        float v[16];
        #pragma unroll
        for (int n = 0; n < N_LEVELS; n++) {
            float sg = 0.f, sc = 0.f;
            #pragma unroll
            for (int j = 0; j < 4; j++) {
                float wv = W[n * D_MODEL + 4*t + j];
                Wr[n][j] = wv;
                sg = fmaf(lw[j], wv, sg);
                sc = fmaf(lb[j], wv, sc);
            }
            v[n] = sg; v[8 + n] = sc;
        }
        #pragma unroll
        for (int off = 16; off > 0; off >>= 1)
            #pragma unroll
            for (int k = 0; k < 16; k++)
                v[k] += __shfl_xor_sync(0xFFFFFFFFu, v[k], off);
        if (L == 0)
            #pragma unroll
            for (int k = 0; k < 16; k++) tmp[w][k] = v[k];
        __syncthreads();
        if (t < 16) {
            float s = 0.f;
            #pragma unroll
            for (int ww = 0; ww < 8; ww++) s += tmp[ww][t];
            if (t < 8) sG[t] = s; else sC[t - 8] = s;
        }
        __syncthreads();
    }
    // write centered packed weights: g'[n][d] = ln_w[d]*W[n][d] - G_n/D
    #pragma unroll
    for (int n = 0; n < N_LEVELS; n++) {
        float gn = sG[n] * INV_D;
        float g0 = fmaf(lw[0], Wr[n][0], -gn);
        float g1 = fmaf(lw[1], Wr[n][1], -gn);
        float g2 = fmaf(lw[2], Wr[n][2], -gn);
        float g3 = fmaf(lw[3], Wr[n][3], -gn);
        longlong2 p;
        p.x = (long long)pack2(g0, g1);
        p.y = (long long)pack2(g2, g3);
        gw[t * 8 + n] = p;
    }
    __syncthreads();

    // ================= main: one 256-row tile per block =================
    const size_t rowbase = (size_t)blockIdx.x * TILE_ROWS;
    const uint32_t tile_s = (uint32_t)__cvta_generic_to_shared(smem);
    const int rsub = 2 * w + (L >> 4);       // this lane's base row within stripes
    const int cq   = (L & 15);               // 16B quad within the 64-col chunk

    // issue a chunk into buffer b (16 cp.async of 16B per thread)
    auto issue = [&](int chunk, int b) {
        const int c0 = chunk * CHUNK_COLS;
        #pragma unroll
        for (int u = 0; u < 16; u++) {
            int r = u * 16 + rsub;
            size_t gr = rowbase + r;
            if (gr >= (size_t)rows) gr = rows - 1;   // clamp (duplicate load, never read OOB)
            const float* src = x + gr * D_MODEL + c0 + cq * 4;
            uint32_t dst = tile_s + b * TILE_BUF_B + r * ROW_STRIDE_B + cq * 16;
            cp16(dst, src);
        }
    };

    issue(0, 0);
    asm volatile("cp.async.commit_group;" ::: "memory");
    issue(1, 1);
    asm volatile("cp.async.commit_group;" ::: "memory");

    ull s2 = 0, q2 = 0, d2[N_LEVELS];
    #pragma unroll
    for (int n = 0; n < N_LEVELS; n++) d2[n] = 0;

    const char* myrow = smem + (size_t)t * ROW_STRIDE_B;

    for (int k = 0; k < N_CHUNKS; k++) {
        asm volatile("cp.async.wait_group 1;" ::: "memory");
        __syncthreads();                              // chunk k visible to all

        const longlong2* trow =
            (const longlong2*)(myrow + (k & 1) * TILE_BUF_B);
        const longlong2* gq = gw + k * 16 * 8;
        #pragma unroll
        for (int qq = 0; qq < 16; qq++) {
            longlong2 xv = trow[qq];
            ull a = (ull)xv.x, bb = (ull)xv.y;
            s2 = add2(s2, add2(a, bb));
            q2 = fma2(a, a, q2);
            q2 = fma2(bb, bb, q2);
            #pragma unroll
            for (int n = 0; n < N_LEVELS; n++) {
                longlong2 g = gq[qq * 8 + n];         // uniform broadcast LDS
                d2[n] = fma2(a,  (ull)g.x, d2[n]);
                d2[n] = fma2(bb, (ull)g.y, d2[n]);
            }
        }
        __syncthreads();                              // everyone done reading buf k&1
        if (k + 2 < N_CHUNKS) issue(k + 2, k & 1);
        asm volatile("cp.async.commit_group;" ::: "memory");  // may be empty: keeps group count uniform
    }

    // ================= epilogue: per-thread finalize, no reduction =================
    size_t grow = rowbase + t;
    if (grow < (size_t)rows) {
        float lo, hi;
        unpack2(s2, lo, hi); float sum = lo + hi;
        unpack2(q2, lo, hi); float sumsq = lo + hi;
        float mean = sum * INV_D;
        float var  = fmaf(sumsq, INV_D, -mean * mean);
        float rstd = rsqrtf(var + LN_EPS);
        float o[N_LEVELS];
        #pragma unroll
        for (int n = 0; n < N_LEVELS; n++) {
            unpack2(d2[n], lo, hi);
            float z = fmaf(rstd, lo + hi, sC[n]);     // centered dot: mean already folded
            o[n] = rintf(HALF_L * tanhf(z));          // round half-to-even, matches jnp.round
        }
        float4* op = (float4*)(out + grow * N_LEVELS);
        op[0] = make_float4(o[0], o[1], o[2], o[3]);
        op[1] = make_float4(o[4], o[5], o[6], o[7]);
    }
}

extern "C" void kernel_launch(void* const* d_in, const int* in_sizes, int n_in,
                              void* d_out, int out_size) {
    const float* regrs = (const float*)d_in[0];
    const float* ln_w  = (const float*)d_in[1];
    const float* ln_b  = (const float*)d_in[2];
    const float* W     = (const float*)d_in[3];
    float* out = (float*)d_out;

    int rows = in_sizes[0] / D_MODEL;        // 32768
    int grid = (rows + TILE_ROWS - 1) / TILE_ROWS;  // 128

    // opt-in to >48KB dynamic smem; first call is the (uncaptured) correctness run
    static bool smem_ok = false;
    if (!smem_ok) {
        cudaFuncSetAttribute(fsq_kernel,
                             cudaFuncAttributeMaxDynamicSharedMemorySize, SMEM_TOTAL);
        smem_ok = true;
    }

    fsq_kernel<<<grid, TPB, SMEM_TOTAL>>>(regrs, ln_w, ln_b, W, out, rows);
}

// round 7
// speedup vs baseline: 2.4238x; 1.1233x over previous
#include <cuda_runtime.h>
#include <cstdint>

#define D_MODEL   1024
#define N_LEVELS  8
#define TPB       128                 // 4 warps; thread t = row t of the tile
#define TILE_ROWS 128
#define CHUNK_COLS 64
#define N_CHUNKS  16                  // 1024 / 64
#define ROW_STRIDE_F 68               // 64 + 4 pad -> phase-conflict-free LDS.128
#define ROW_STRIDE_B (ROW_STRIDE_F * 4)        // 272 B
#define WARP_BUF_B (32 * ROW_STRIDE_B)         // 8704 B per buffer
#define HALF_L 3.9960f
#define LN_EPS 1e-5f
#define INV_D  (1.0f / 1024.0f)

// dynamic smem layout
#define OFF_BUFS 0                              // 4 warps x 2 bufs x 8704 = 69632
#define OFF_GW   (4 * 2 * WARP_BUF_B)           // 69632: longlong2 gw[256][8] = 32768
#define OFF_CV   (OFF_GW + 256 * 8 * 16)        // 102400: float G[8], C[8]
#define OFF_TMP  (OFF_CV + 64)                  // 102464: float tmp[4][16]
#define SMEM_TOTAL (OFF_TMP + 256)              // 102720 -> 2 CTAs/SM

typedef unsigned long long ull;

__device__ __forceinline__ ull pack2(float lo, float hi) {
    ull r; asm("mov.b64 %0, {%1, %2};" : "=l"(r) : "f"(lo), "f"(hi)); return r;
}
__device__ __forceinline__ void unpack2(ull p, float& lo, float& hi) {
    asm("mov.b64 {%0, %1}, %2;" : "=f"(lo), "=f"(hi) : "l"(p));
}
__device__ __forceinline__ ull fma2(ull a, ull b, ull c) {
    ull d; asm("fma.rn.f32x2 %0, %1, %2, %3;" : "=l"(d) : "l"(a), "l"(b), "l"(c)); return d;
}
__device__ __forceinline__ ull add2(ull a, ull b) {
    ull d; asm("add.rn.f32x2 %0, %1, %2;" : "=l"(d) : "l"(a), "l"(b)); return d;
}
__device__ __forceinline__ void cp16(uint32_t dst, const float* src) {
    asm volatile("cp.async.cg.shared.global [%0], [%1], 16;" :: "r"(dst), "l"(src));
}

__global__ __launch_bounds__(TPB) void fsq_kernel(
    const float* __restrict__ x,     // [rows, 1024]
    const float* __restrict__ ln_w,  // [1024]
    const float* __restrict__ ln_b,  // [1024]
    const float* __restrict__ W,     // [8, 1024]
    float* __restrict__ out,         // [rows, 8]
    int rows)
{
    extern __shared__ char smem[];
    longlong2* gw    = (longlong2*)(smem + OFF_GW);   // [quad 0..255][level 0..7]
    float* sG        = (float*)(smem + OFF_CV);
    float* sC        = (float*)(smem + OFF_CV) + 8;
    float (*tmp)[16] = (float(*)[16])(smem + OFF_TMP);

    const int t = threadIdx.x;          // 0..127
    const int w = t >> 5, L = t & 31;

    // ===== preamble pass 1: G_n = sum(ln_w*W[n]), C_n = sum(ln_b*W[n]) =====
    {
        float v[16];
        #pragma unroll
        for (int k = 0; k < 16; k++) v[k] = 0.f;
        #pragma unroll
        for (int h = 0; h < 2; h++) {                 // quads t and t+128
            const int q = t + h * 128;
            float lw4[4], lb4[4];
            #pragma unroll
            for (int j = 0; j < 4; j++) { lw4[j] = ln_w[4*q + j]; lb4[j] = ln_b[4*q + j]; }
            #pragma unroll
            for (int n = 0; n < N_LEVELS; n++) {
                #pragma unroll
                for (int j = 0; j < 4; j++) {
                    float wv = W[n * D_MODEL + 4*q + j];
                    v[n]     = fmaf(lw4[j], wv, v[n]);
                    v[8 + n] = fmaf(lb4[j], wv, v[8 + n]);
                }
            }
        }
        #pragma unroll
        for (int off = 16; off > 0; off >>= 1)
            #pragma unroll
            for (int k = 0; k < 16; k++)
                v[k] += __shfl_xor_sync(0xFFFFFFFFu, v[k], off);
        if (L == 0)
            #pragma unroll
            for (int k = 0; k < 16; k++) tmp[w][k] = v[k];
        __syncthreads();
        if (t < 16) {
            float s = tmp[0][t] + tmp[1][t] + tmp[2][t] + tmp[3][t];
            if (t < 8) sG[t] = s; else sC[t - 8] = s;
        }
        __syncthreads();
    }
    // ===== preamble pass 2: centered weights g'[n][d] = ln_w*W - G_n/D =====
    #pragma unroll
    for (int h = 0; h < 2; h++) {
        const int q = t + h * 128;
        float lw4[4];
        #pragma unroll
        for (int j = 0; j < 4; j++) lw4[j] = ln_w[4*q + j];
        #pragma unroll
        for (int n = 0; n < N_LEVELS; n++) {
            float gn = sG[n] * INV_D;
            float g0 = fmaf(lw4[0], W[n * D_MODEL + 4*q + 0], -gn);
            float g1 = fmaf(lw4[1], W[n * D_MODEL + 4*q + 1], -gn);
            float g2 = fmaf(lw4[2], W[n * D_MODEL + 4*q + 2], -gn);
            float g3 = fmaf(lw4[3], W[n * D_MODEL + 4*q + 3], -gn);
            longlong2 p;
            p.x = (long long)pack2(g0, g1);
            p.y = (long long)pack2(g2, g3);
            gw[q * 8 + n] = p;
        }
    }
    __syncthreads();   // gw visible to all warps; last block barrier

    // ===== mainloop: per-warp private double-buffered pipeline =====
    const size_t tilebase = (size_t)blockIdx.x * TILE_ROWS;
    const uint32_t smem_u = (uint32_t)__cvta_generic_to_shared(smem);
    const uint32_t mybufs = smem_u + w * 2 * WARP_BUF_B;
    const int rsub = (L >> 4);          // 0/1: which of the 2 rows this lane helps load
    const int cq   = (L & 15);          // 16B quad within 64-col chunk

    auto issue = [&](int chunk, int b) {
        const int c0 = chunk * CHUNK_COLS;
        #pragma unroll
        for (int u = 0; u < 16; u++) {
            int rin = 2 * u + rsub;                       // row-in-warp 0..31
            size_t grow = tilebase + 32 * w + rin;
            if (grow >= (size_t)rows) grow = rows - 1;    // clamp, never OOB
            const float* src = x + grow * D_MODEL + c0 + cq * 4;
            uint32_t dst = mybufs + b * WARP_BUF_B + rin * ROW_STRIDE_B + cq * 16;
            cp16(dst, src);
        }
    };

    issue(0, 0);
    asm volatile("cp.async.commit_group;" ::: "memory");
    issue(1, 1);
    asm volatile("cp.async.commit_group;" ::: "memory");

    ull s2 = 0, q2 = 0, d2[N_LEVELS];
    #pragma unroll
    for (int n = 0; n < N_LEVELS; n++) d2[n] = 0;

    for (int k = 0; k < N_CHUNKS; k++) {
        asm volatile("cp.async.wait_group 1;" ::: "memory");
        __syncwarp();                                     // warp-local visibility

        const longlong2* trow = (const longlong2*)
            (smem + (size_t)(w * 2 + (k & 1)) * WARP_BUF_B + (size_t)L * ROW_STRIDE_B);
        const longlong2* gq = gw + k * 16 * 8;
        #pragma unroll
        for (int qq = 0; qq < 16; qq++) {
            longlong2 xv = trow[qq];
            ull a = (ull)xv.x, bb = (ull)xv.y;
            s2 = add2(s2, add2(a, bb));
            q2 = fma2(a, a, q2);
            q2 = fma2(bb, bb, q2);
            #pragma unroll
            for (int n = 0; n < N_LEVELS; n++) {
                longlong2 g = gq[qq * 8 + n];             // uniform broadcast LDS
                d2[n] = fma2(a,  (ull)g.x, d2[n]);
                d2[n] = fma2(bb, (ull)g.y, d2[n]);
            }
        }
        __syncwarp();                                     // all lanes done reading buf
        if (k + 2 < N_CHUNKS) issue(k + 2, k & 1);
        asm volatile("cp.async.commit_group;" ::: "memory");  // uniform group count
    }

    // ===== epilogue: per-thread finalize (thread t = tile row t) =====
    size_t grow = tilebase + t;
    if (grow < (size_t)rows) {
        float lo, hi;
        unpack2(s2, lo, hi); float sum   = lo + hi;
        unpack2(q2, lo, hi); float sumsq = lo + hi;
        float mean = sum * INV_D;
        float var  = fmaf(sumsq, INV_D, -mean * mean);
        float rstd = rsqrtf(var + LN_EPS);
        float o[N_LEVELS];
        #pragma unroll
        for (int n = 0; n < N_LEVELS; n++) {
            unpack2(d2[n], lo, hi);
            float z = fmaf(rstd, lo + hi, sC[n]);         // mean folded into centered g'
            o[n] = rintf(HALF_L * tanhf(z));
        }
        float4* op = (float4*)(out + grow * N_LEVELS);
        op[0] = make_float4(o[0], o[1], o[2], o[3]);
        op[1] = make_float4(o[4], o[5], o[6], o[7]);
    }
}

extern "C" void kernel_launch(void* const* d_in, const int* in_sizes, int n_in,
                              void* d_out, int out_size) {
    const float* regrs = (const float*)d_in[0];
    const float* ln_w  = (const float*)d_in[1];
    const float* ln_b  = (const float*)d_in[2];
    const float* W     = (const float*)d_in[3];
    float* out = (float*)d_out;

    int rows = in_sizes[0] / D_MODEL;                  // 32768
    int grid = (rows + TILE_ROWS - 1) / TILE_ROWS;     // 256

    cudaFuncSetAttribute(fsq_kernel,
                         cudaFuncAttributeMaxDynamicSharedMemorySize, SMEM_TOTAL);
    fsq_kernel<<<grid, TPB, SMEM_TOTAL>>>(regrs, ln_w, ln_b, W, out, rows);
}